// round 3
// baseline (speedup 1.0000x reference)
#include <cuda_runtime.h>
#include <cstdint>

// Kuramoto oscillators: B=32, N=2048, K=8, T=20.
// R3: cluster of 4 CTAs per batch (grid=128). Full replicated phase array in
// each CTA's smem, double buffered. Per step: gather 8 neighbors (local LDS),
// 8x __sinf, update, broadcast own phase to 3 peers (st.shared::cluster),
// then a distributed mbarrier sync (thread0 release-arrives on all 4 CTAs'
// barriers after __syncthreads; everyone acquire-waits locally) instead of
// barrier.cluster (~490cyc -> ~60-90cyc wakeup).
// Duplicate scatter targets: LAST k wins; n = #distinct nonzero targets.
// eps/n is folded into the weights (eps=1, anneal=0).

#define Nn 2048
#define Kk 8
#define Bb 32
#define Tt 20
#define CSZ 4
#define THREADS 512
#define NPC (Nn / CSZ)

#define TWO_PI     6.28318530717958647692f
#define INV_TWO_PI 0.15915494309189533577f

__device__ __forceinline__ uint32_t smem_u32(const void* p) {
    uint32_t a;
    asm("{ .reg .u64 t; cvta.to.shared.u64 t, %1; cvt.u32.u64 %0, t; }"
        : "=r"(a) : "l"(p));
    return a;
}

__device__ __forceinline__ uint32_t mapa_u32(uint32_t laddr, uint32_t rank) {
    uint32_t r;
    asm("mapa.shared::cluster.u32 %0, %1, %2;" : "=r"(r) : "r"(laddr), "r"(rank));
    return r;
}

__device__ __forceinline__ void st_cluster_f32(uint32_t raddr, float v) {
    asm volatile("st.shared::cluster.f32 [%0], %1;" :: "r"(raddr), "f"(v) : "memory");
}

__device__ __forceinline__ void mbar_arrive_remote(uint32_t raddr) {
    asm volatile("mbarrier.arrive.release.cluster.shared::cluster.b64 _, [%0];"
                 :: "r"(raddr) : "memory");
}

__device__ __forceinline__ void mbar_arrive_local(uint32_t laddr) {
    asm volatile("{ .reg .b64 s; mbarrier.arrive.release.cluster.shared::cta.b64 s, [%0]; }"
                 :: "r"(laddr) : "memory");
}

__device__ __forceinline__ void mbar_wait_cluster(uint32_t laddr, uint32_t parity) {
    uint32_t done;
    asm volatile(
        "{ .reg .pred p;\n"
        "  mbarrier.try_wait.parity.acquire.cluster.shared::cta.b64 p, [%1], %2;\n"
        "  selp.b32 %0, 1, 0, p; }"
        : "=r"(done) : "r"(laddr), "r"(parity) : "memory");
    if (!done) {
        asm volatile(
            "{ .reg .pred p;\n"
            "WL_%=:\n"
            "  mbarrier.try_wait.parity.acquire.cluster.shared::cta.b64 p, [%0], %1;\n"
            "  @p bra.uni WD_%=;\n"
            "  bra.uni WL_%=;\n"
            "WD_%=: }"
            :: "r"(laddr), "r"(parity) : "memory");
    }
}

__global__ void __launch_bounds__(THREADS, 1) __cluster_dims__(CSZ, 1, 1)
osc_kernel(const float* __restrict__ coupling,   // [B,N,K]
           const float* __restrict__ phase0,     // [B,N]
           const float* __restrict__ omega,      // [B,N]
           const int*   __restrict__ conn,       // [N,K]
           float*       __restrict__ out)        // [T+1,B,N]
{
    __shared__ float th[2][Nn];                   // replicated reduced phases
    __shared__ __align__(8) unsigned long long mbar;

    uint32_t rank;
    asm("mov.u32 %0, %%cluster_ctarank;" : "=r"(rank));
    const int b   = blockIdx.x / CSZ;
    const int tid = threadIdx.x;
    const int n   = (int)rank * NPC + tid;

    // ---- mbarrier init (count = CSZ arrivals per phase) ----
    const uint32_t mbar_l = smem_u32(&mbar);
    if (tid == 0) {
        asm volatile("mbarrier.init.shared.b64 [%0], %1;"
                     :: "r"(mbar_l), "r"((uint32_t)CSZ) : "memory");
    }

    // ---- prologue: dedup couplings, fold eps/n into weights ----
    float w[Kk];
    int   off[Kk];
    int idx[Kk];
    #pragma unroll
    for (int k = 0; k < Kk; ++k) idx[k] = conn[n * Kk + k];

    int cnt = 0;
    #pragma unroll
    for (int k = 0; k < Kk; ++k) {
        bool win = true;
        #pragma unroll
        for (int k2 = k + 1; k2 < Kk; ++k2) win = win && (idx[k2] != idx[k]);
        const float c = coupling[((size_t)b * Nn + n) * Kk + k];
        w[k]   = win ? c : 0.0f;
        off[k] = idx[k];
        cnt += (win && (c != 0.0f)) ? 1 : 0;
    }
    const float inv = (cnt > 0) ? (1.0f / (float)cnt) : 0.0f;
    #pragma unroll
    for (int k = 0; k < Kk; ++k) w[k] *= inv;    // fold eps/n into weights

    float p  = phase0[(size_t)b * Nn + n];
    const float om = omega[(size_t)b * Nn + n];
    out[(size_t)b * Nn + n] = p;                  // t=0 slice

    // fill full local copy of th[0]
    #pragma unroll
    for (int j = 0; j < CSZ; ++j) {
        const int m  = tid + j * THREADS;
        const float q = phase0[(size_t)b * Nn + m];
        th[0][m] = q - TWO_PI * rintf(q * INV_TWO_PI);
    }
    float pr = p - TWO_PI * rintf(p * INV_TWO_PI);

    // hoist remote addresses: value slots (2 buffers x 3 peers) + peer barriers
    uint32_t vr[2][CSZ - 1];
    uint32_t br[CSZ - 1];
    {
        const uint32_t a0 = smem_u32(&th[0][n]);
        const uint32_t a1 = smem_u32(&th[1][n]);
        int q = 0;
        #pragma unroll
        for (int r = 0; r < CSZ; ++r) {
            if ((uint32_t)r != rank) {
                vr[0][q] = mapa_u32(a0, (uint32_t)r);
                vr[1][q] = mapa_u32(a1, (uint32_t)r);
                br[q]    = mapa_u32(mbar_l, (uint32_t)r);
                ++q;
            }
        }
    }

    __syncthreads();   // local th[0] complete + mbarrier init visible locally
    // cluster-wide: all CTAs' mbarriers initialized before any remote arrive
    asm volatile("barrier.cluster.arrive.aligned;" ::: "memory");
    asm volatile("barrier.cluster.wait.aligned;"   ::: "memory");

    // ---- time stepping ----
    #pragma unroll 1
    for (int t = 0; t < Tt; ++t) {
        const float* __restrict__ cur = th[t & 1];

        float acc = 0.0f;
        #pragma unroll
        for (int k = 0; k < Kk; ++k)
            acc += w[k] * __sinf(cur[off[k]] - pr);   // arg in [-2pi, 2pi]

        p += acc + om;
        const float prn = p - TWO_PI * rintf(p * INV_TWO_PI);
        pr = prn;

        // publish reduced phase: own buffer + 3 peers
        th[(t + 1) & 1][n] = prn;
        const int nb = (t + 1) & 1;
        #pragma unroll
        for (int q = 0; q < CSZ - 1; ++q) st_cluster_f32(vr[nb][q], prn);

        // global output (latency hidden behind the sync)
        out[(size_t)(t + 1) * (Bb * Nn) + (size_t)b * Nn + n] = p;

        // distributed sync: all stores done (CTA scope), then thread0
        // release-arrives on every CTA's barrier; everyone acquire-waits.
        __syncthreads();
        if (tid == 0) {
            #pragma unroll
            for (int q = 0; q < CSZ - 1; ++q) mbar_arrive_remote(br[q]);
            mbar_arrive_local(mbar_l);
        }
        mbar_wait_cluster(mbar_l, (uint32_t)(t & 1));
    }
}

extern "C" void kernel_launch(void* const* d_in, const int* in_sizes, int n_in,
                              void* d_out, int out_size)
{
    const float* coupling = (const float*)d_in[0];   // [B,N,K] f32
    const float* phase0   = (const float*)d_in[1];   // [B,N]   f32
    const float* omega    = (const float*)d_in[2];   // [B,N]   f32
    const int*   conn     = (const int*)  d_in[3];   // [N,K]   i32
    float*       out      = (float*)d_out;           // [T+1,B,N] f32

    osc_kernel<<<Bb * CSZ, THREADS>>>(coupling, phase0, omega, conn, out);
}

// round 4
// speedup vs baseline: 1.5792x; 1.5792x over previous
#include <cuda_runtime.h>
#include <cstdint>

// Kuramoto oscillators: B=32, N=2048, K=8, T=20.
// R4: cluster of 4 CTAs per batch (grid=128). Replicated double-buffered
// phase array per CTA. Per step: gather 8 neighbors (local LDS), 8x __sinf,
// update, STS own 512-phase slice, __syncthreads, then 3 threads each issue
// ONE 2KB cp.async.bulk (shared::cta -> shared::cluster) to a peer's buffer,
// signaling the peer's mbarrier via complete_tx. Own mbarrier expects 6144
// bytes (armed by thread0). Next step begins with try_wait.parity.acquire
// (~90cyc wakeup) instead of barrier.cluster (~490cyc) + scalar DSMEM drain.
// Duplicate scatter targets: LAST k wins; n = #distinct nonzero targets.
// eps/n folded into weights (eps=1, anneal=0).

#define Nn 2048
#define Kk 8
#define Bb 32
#define Tt 20
#define CSZ 4
#define THREADS 512
#define NPC (Nn / CSZ)            // 512 oscillators per CTA
#define SLICE_BYTES (NPC * 4)     // 2048 bytes
#define EXPECT_BYTES ((CSZ - 1) * SLICE_BYTES)  // 6144 incoming per step

#define TWO_PI     6.28318530717958647692f
#define INV_TWO_PI 0.15915494309189533577f

__device__ __forceinline__ uint32_t smem_u32(const void* p) {
    uint32_t a;
    asm("{ .reg .u64 t; cvta.to.shared.u64 t, %1; cvt.u32.u64 %0, t; }"
        : "=r"(a) : "l"(p));
    return a;
}

__device__ __forceinline__ uint32_t mapa_u32(uint32_t laddr, uint32_t rank) {
    uint32_t r;
    asm("mapa.shared::cluster.u32 %0, %1, %2;" : "=r"(r) : "r"(laddr), "r"(rank));
    return r;
}

__device__ __forceinline__ void mbar_init(uint32_t laddr, uint32_t count) {
    asm volatile("mbarrier.init.shared.b64 [%0], %1;" :: "r"(laddr), "r"(count) : "memory");
}

__device__ __forceinline__ void mbar_arrive_expect_tx(uint32_t laddr, uint32_t tx) {
    asm volatile("mbarrier.arrive.expect_tx.shared.b64 _, [%0], %1;"
                 :: "r"(laddr), "r"(tx) : "memory");
}

__device__ __forceinline__ void bulk_s2s_cluster(uint32_t dst_cluster,
                                                 uint32_t src_cta,
                                                 uint32_t bytes,
                                                 uint32_t rmbar_cluster) {
    asm volatile(
        "cp.async.bulk.shared::cluster.shared::cta.mbarrier::complete_tx::bytes "
        "[%0], [%1], %2, [%3];"
        :: "r"(dst_cluster), "r"(src_cta), "r"(bytes), "r"(rmbar_cluster)
        : "memory");
}

__device__ __forceinline__ void mbar_wait(uint32_t laddr, uint32_t parity) {
    uint32_t done;
    asm volatile(
        "{ .reg .pred p;\n"
        "  mbarrier.try_wait.parity.acquire.cluster.shared::cta.b64 p, [%1], %2;\n"
        "  selp.b32 %0, 1, 0, p; }"
        : "=r"(done) : "r"(laddr), "r"(parity) : "memory");
    if (!done) {
        asm volatile(
            "{ .reg .pred p;\n"
            "WL_%=:\n"
            "  mbarrier.try_wait.parity.acquire.cluster.shared::cta.b64 p, [%0], %1, 0x989680;\n"
            "  @p bra.uni WD_%=;\n"
            "  bra.uni WL_%=;\n"
            "WD_%=: }"
            :: "r"(laddr), "r"(parity) : "memory");
    }
}

__global__ void __launch_bounds__(THREADS, 1) __cluster_dims__(CSZ, 1, 1)
osc_kernel(const float* __restrict__ coupling,   // [B,N,K]
           const float* __restrict__ phase0,     // [B,N]
           const float* __restrict__ omega,      // [B,N]
           const int*   __restrict__ conn,       // [N,K]
           float*       __restrict__ out)        // [T+1,B,N]
{
    __shared__ __align__(16) float th[2][Nn];                 // replicated reduced phases
    __shared__ __align__(8)  unsigned long long mbar[2];      // one per buffer

    uint32_t rank;
    asm("mov.u32 %0, %%cluster_ctarank;" : "=r"(rank));
    const int b   = blockIdx.x / CSZ;
    const int tid = threadIdx.x;
    const int n   = (int)rank * NPC + tid;

    const uint32_t mb_l[2] = { smem_u32(&mbar[0]), smem_u32(&mbar[1]) };
    if (tid == 0) {
        mbar_init(mb_l[0], 1);   // single arrive (the arming thread)
        mbar_init(mb_l[1], 1);
    }

    // ---- prologue: dedup couplings, fold eps/n into weights ----
    float w[Kk];
    int   off[Kk];
    int idx[Kk];
    #pragma unroll
    for (int k = 0; k < Kk; ++k) idx[k] = conn[n * Kk + k];

    int cnt = 0;
    #pragma unroll
    for (int k = 0; k < Kk; ++k) {
        bool win = true;
        #pragma unroll
        for (int k2 = k + 1; k2 < Kk; ++k2) win = win && (idx[k2] != idx[k]);
        const float c = coupling[((size_t)b * Nn + n) * Kk + k];
        w[k]   = win ? c : 0.0f;
        off[k] = idx[k];
        cnt += (win && (c != 0.0f)) ? 1 : 0;
    }
    const float inv = (cnt > 0) ? (1.0f / (float)cnt) : 0.0f;
    #pragma unroll
    for (int k = 0; k < Kk; ++k) w[k] *= inv;

    float p  = phase0[(size_t)b * Nn + n];
    const float om = omega[(size_t)b * Nn + n];
    out[(size_t)b * Nn + n] = p;                 // t=0 slice

    // each CTA fills its FULL th[0] locally from gmem (no comms needed)
    #pragma unroll
    for (int j = 0; j < CSZ; ++j) {
        const int m  = tid + j * THREADS;
        const float q = phase0[(size_t)b * Nn + m];
        th[0][m] = q - TWO_PI * rintf(q * INV_TWO_PI);
    }
    float pr = p - TWO_PI * rintf(p * INV_TWO_PI);

    // hoisted addresses for the bulk sends: this CTA's slice in both buffers,
    // the 3 peers' matching destination slices, and the peers' mbarriers.
    const uint32_t src_l[2] = { smem_u32(&th[0][rank * NPC]),
                                smem_u32(&th[1][rank * NPC]) };
    // per-sender-thread (tid<3) peer rank
    uint32_t peer = 0, dst_r[2] = {0, 0}, mbr_r[2] = {0, 0};
    if (tid < CSZ - 1) {
        peer = (uint32_t)tid < rank ? (uint32_t)tid : (uint32_t)(tid + 1);
        dst_r[0] = mapa_u32(src_l[0], peer);
        dst_r[1] = mapa_u32(src_l[1], peer);
        mbr_r[0] = mapa_u32(mb_l[0], peer);
        mbr_r[1] = mapa_u32(mb_l[1], peer);
    }

    __syncthreads();   // local th[0] + mbarrier init complete (CTA scope)
    // cluster-wide: all mbarriers initialized before any peer bulk can signal
    asm volatile("barrier.cluster.arrive.aligned;" ::: "memory");
    asm volatile("barrier.cluster.wait.aligned;"   ::: "memory");

    uint32_t par[2] = {0, 0};   // parity trackers per buffer mbarrier

    // ---- time stepping ----
    #pragma unroll 1
    for (int t = 0; t < Tt; ++t) {
        const int c  = t & 1;
        const int nb = c ^ 1;

        if (t > 0) {           // wait for peers' slices of buffer c
            mbar_wait(mb_l[c], par[c]);
            par[c] ^= 1u;
        }

        const float* __restrict__ cur = th[c];

        float acc = 0.0f;
        #pragma unroll
        for (int k = 0; k < Kk; ++k)
            acc += w[k] * __sinf(cur[off[k]] - pr);   // arg in [-2pi, 2pi]

        p += acc + om;
        const float prn = p - TWO_PI * rintf(p * INV_TWO_PI);
        pr = prn;

        // own slice into own next buffer + global output
        th[nb][n] = prn;
        out[(size_t)(t + 1) * (Bb * Nn) + (size_t)b * Nn + n] = p;

        if (t < Tt - 1) {
            __syncthreads();   // slice complete before the bulk engine reads it
            if (tid < CSZ - 1) {
                asm volatile("fence.proxy.async.shared::cta;" ::: "memory");
                bulk_s2s_cluster(dst_r[nb], src_l[nb], SLICE_BYTES, mbr_r[nb]);
            }
            if (tid == 0) {
                mbar_arrive_expect_tx(mb_l[nb], EXPECT_BYTES);
            }
        }
    }
}

extern "C" void kernel_launch(void* const* d_in, const int* in_sizes, int n_in,
                              void* d_out, int out_size)
{
    const float* coupling = (const float*)d_in[0];   // [B,N,K] f32
    const float* phase0   = (const float*)d_in[1];   // [B,N]   f32
    const float* omega    = (const float*)d_in[2];   // [B,N]   f32
    const int*   conn     = (const int*)  d_in[3];   // [N,K]   i32
    float*       out      = (float*)d_out;           // [T+1,B,N] f32

    osc_kernel<<<Bb * CSZ, THREADS>>>(coupling, phase0, omega, conn, out);
}